// round 12
// baseline (speedup 1.0000x reference)
#include <cuda_runtime.h>
#include <cuda_bf16.h>
#include <math.h>
#include <cstdint>

// Problem constants (fixed shapes from reference)
#define B_  4
#define T_  2048
#define C_  1024
#define H_  16
#define HD_ 64
#define M_ROWS (B_ * T_)          // 8192
#define QKV_N  (3 * C_)           // 3072

// -------- scratch (device globals; no allocation allowed) --------
// g_q/g_k are stored with k-permutation p(j)=((j&3)<<1)|(j>>2) within each
// 8-block of the head dim (QK dot products are invariant since both sides use it).
__device__ uint32_t g_q[(size_t)B_ * H_ * T_ * HD_];   // tf32 bits, roped, *0.125*log2e, k-permuted
__device__ uint32_t g_k[(size_t)B_ * H_ * T_ * HD_];   // tf32 bits, roped, k-permuted
__device__ uint32_t g_v[(size_t)B_ * H_ * T_ * HD_];   // tf32 bits (natural layout)
__device__ uint32_t g_y[(size_t)M_ROWS * C_];          // tf32 bits (B, T, C)
__device__ uint32_t g_xt[(size_t)M_ROWS * C_];         // tf32(x)
__device__ uint32_t g_wat[(size_t)QKV_N * C_];         // tf32(w_attn)
__device__ uint32_t g_wpt[(size_t)C_ * C_];            // tf32(w_proj)
__device__ float2   g_rt[(size_t)T_ * 32];             // rope cos/sin table

// ---- tf32 / mma / cp.async helpers ----
__device__ __forceinline__ uint32_t f2tf32(float x) {
    uint32_t r; asm("cvt.rna.tf32.f32 %0, %1;" : "=r"(r) : "f"(x)); return r;
}
__device__ __forceinline__ float ex2f(float x) {
    float r; asm("ex2.approx.ftz.f32 %0, %1;" : "=f"(r) : "f"(x)); return r;
}
__device__ __forceinline__ void mma16n8k8(float c[4], const uint32_t a[4], const uint32_t b[2]) {
    asm volatile(
        "mma.sync.aligned.m16n8k8.row.col.f32.tf32.tf32.f32 "
        "{%0,%1,%2,%3}, {%4,%5,%6,%7}, {%8,%9}, {%0,%1,%2,%3};"
        : "+f"(c[0]), "+f"(c[1]), "+f"(c[2]), "+f"(c[3])
        : "r"(a[0]), "r"(a[1]), "r"(a[2]), "r"(a[3]), "r"(b[0]), "r"(b[1]));
}
__device__ __forceinline__ uint32_t smem_u32(const void* p) {
    uint32_t a;
    asm("{ .reg .u64 t; cvta.to.shared.u64 t, %1; cvt.u32.u64 %0, t; }" : "=r"(a) : "l"(p));
    return a;
}
__device__ __forceinline__ void cp16(uint32_t dst, const void* src) {
    asm volatile("cp.async.cg.shared.global [%0], [%1], 16;" :: "r"(dst), "l"(src));
}
#define CP_COMMIT() asm volatile("cp.async.commit_group;" ::: "memory")
#define CP_WAIT1()  asm volatile("cp.async.wait_group 1;" ::: "memory")
#define CP_WAIT0()  asm volatile("cp.async.wait_group 0;" ::: "memory")

// ============================================================================
// input converter: fp32 -> tf32 bits
// ============================================================================
__global__ __launch_bounds__(256) void to_tf32(const float* __restrict__ in,
                                               uint32_t* __restrict__ out, int n)
{
    int i = (blockIdx.x * blockDim.x + threadIdx.x) * 4;
    if (i < n) {
        float4 v = *(const float4*)(in + i);
        *(uint4*)(out + i) = make_uint4(f2tf32(v.x), f2tf32(v.y), f2tf32(v.z), f2tf32(v.w));
    }
}

// ============================================================================
// RoPE table: cos/sin for (t, i) computed once per launch (fp64 accurate)
// ============================================================================
__global__ __launch_bounds__(256) void rope_tab()
{
    int idx = blockIdx.x * blockDim.x + threadIdx.x;
    if (idx >= T_ * 32) return;
    int i = idx & 31;
    int t = idx >> 5;
    double inv = exp2(-(double)i * (13.287712379549449595 / 32.0)); // 10000^(-i/32)
    double ds, dc;
    sincos((double)t * inv, &ds, &dc);
    g_rt[idx] = make_float2((float)dc, (float)ds);
}

// ============================================================================
// Shared GEMM mainloop body (CTA 128x128, BK=32, 8 warps 2x4, 3-stage
// cp.async ring, single sync per tile). Used by gemm_tc and gemm_qkv.
// ============================================================================
#define GEMM_SMEM (24576 * 4)    // 3 stages x (A 4096 + B 4096) words = 96KB

#define GEMM_MAINLOOP(Aptr, Bptr, Kdim)                                          \
    auto cp_tile = [&](int k0, int s) {                                          \
        _Pragma("unroll")                                                        \
        for (int p = 0; p < 4; ++p) {                                            \
            int row = lrow + p * 32;                                             \
            int u = lu ^ (row & 7);                                              \
            cp16(sbase + (uint32_t)(s * 4096 + row * 32 + u * 4) * 4,            \
                 (Aptr) + (size_t)(bm + row) * (Kdim) + k0 + lu * 4);            \
            cp16(sbase + (uint32_t)(12288 + s * 4096 + row * 32 + u * 4) * 4,    \
                 (Bptr) + (size_t)(bn + row) * (Kdim) + k0 + lu * 4);            \
        }                                                                        \
    };                                                                           \
    const int nk = (Kdim) >> 5;                                                  \
    cp_tile(0, 0); CP_COMMIT();                                                  \
    cp_tile(32, 1); CP_COMMIT();                                                 \
    for (int kt = 0; kt < nk; ++kt) {                                            \
        if (kt + 1 < nk) CP_WAIT1(); else CP_WAIT0();                            \
        __syncthreads();                                                         \
        const int cs = kt % 3;                                                   \
        const uint32_t* Asb = sm + cs * 4096;                                    \
        const uint32_t* Bsb = sm + 12288 + cs * 4096;                            \
        _Pragma("unroll")                                                        \
        for (int c8 = 0; c8 < 4; ++c8) {                                         \
            const int u0 = (2 * c8) ^ g;                                         \
            const int u1 = u0 ^ 1;                                               \
            uint32_t af[4][4];                                                   \
            _Pragma("unroll")                                                    \
            for (int mt = 0; mt < 4; ++mt) {                                     \
                const int r0 = wm * 64 + mt * 16 + g;                            \
                af[mt][0] = Asb[r0 * 32 + u0 * 4 + t];                           \
                af[mt][1] = Asb[(r0 + 8) * 32 + u0 * 4 + t];                     \
                af[mt][2] = Asb[r0 * 32 + u1 * 4 + t];                           \
                af[mt][3] = Asb[(r0 + 8) * 32 + u1 * 4 + t];                     \
            }                                                                    \
            uint32_t bf[4][2];                                                   \
            _Pragma("unroll")                                                    \
            for (int nt = 0; nt < 4; ++nt) {                                     \
                const int n0 = wn * 32 + nt * 8 + g;                             \
                bf[nt][0] = Bsb[n0 * 32 + u0 * 4 + t];                           \
                bf[nt][1] = Bsb[n0 * 32 + u1 * 4 + t];                           \
            }                                                                    \
            _Pragma("unroll")                                                    \
            for (int mt = 0; mt < 4; ++mt)                                       \
                _Pragma("unroll")                                                \
                for (int nt = 0; nt < 4; ++nt)                                   \
                    mma16n8k8(acc[mt][nt], af[mt], bf[nt]);                      \
        }                                                                        \
        if (kt + 2 < nk) { cp_tile((kt + 2) << 5, (kt + 2) % 3); CP_COMMIT(); }  \
    }

// ============================================================================
// Generic GEMM (NT), fp32 output — used for the output projection.
// ============================================================================
__global__ void __launch_bounds__(256, 2) gemm_tc(
    const uint32_t* __restrict__ A, const uint32_t* __restrict__ Bm,
    float* __restrict__ C, int M, int N, int K)
{
    extern __shared__ uint32_t sm[];
    const uint32_t sbase = smem_u32(sm);

    const int tid  = threadIdx.x;
    const int lane = tid & 31;
    const int wid  = tid >> 5;
    const int wm = wid & 1;
    const int wn = wid >> 1;
    const int g = lane >> 2;
    const int t = lane & 3;
    const int bm = blockIdx.y * 128;
    const int bn = blockIdx.x * 128;
    const int lrow = tid >> 3;
    const int lu   = tid & 7;

    float acc[4][4][4];
#pragma unroll
    for (int mt = 0; mt < 4; ++mt)
#pragma unroll
        for (int nt = 0; nt < 4; ++nt)
#pragma unroll
            for (int q = 0; q < 4; ++q) acc[mt][nt][q] = 0.0f;

    GEMM_MAINLOOP(A, Bm, K)

#pragma unroll
    for (int mt = 0; mt < 4; ++mt) {
        const int row = bm + wm * 64 + mt * 16 + g;
#pragma unroll
        for (int nt = 0; nt < 4; ++nt) {
            const int col = bn + wn * 32 + nt * 8 + 2 * t;
            *(float2*)(C + (size_t)row * N + col)       = make_float2(acc[mt][nt][0], acc[mt][nt][1]);
            *(float2*)(C + (size_t)(row + 8) * N + col) = make_float2(acc[mt][nt][2], acc[mt][nt][3]);
        }
    }
}

// ============================================================================
// QKV GEMM with FUSED RoPE epilogue. N=3072; each CTA's 128-col slab lies in
// one section (q/k/v). Writes g_q/g_k (roped, tf32, k-permuted) and g_v
// (tf32) directly — no intermediate qkv buffer, no rope kernel.
// ============================================================================
__global__ void __launch_bounds__(256, 2) gemm_qkv(
    const uint32_t* __restrict__ A, const uint32_t* __restrict__ Bm)
{
    extern __shared__ uint32_t sm[];
    const uint32_t sbase = smem_u32(sm);

    const int tid  = threadIdx.x;
    const int lane = tid & 31;
    const int wid  = tid >> 5;
    const int wm = wid & 1;
    const int wn = wid >> 1;
    const int g = lane >> 2;
    const int t = lane & 3;
    const int bm = blockIdx.y * 128;
    const int bn = blockIdx.x * 128;
    const int lrow = tid >> 3;
    const int lu   = tid & 7;

    float acc[4][4][4];
#pragma unroll
    for (int mt = 0; mt < 4; ++mt)
#pragma unroll
        for (int nt = 0; nt < 4; ++nt)
#pragma unroll
            for (int q = 0; q < 4; ++q) acc[mt][nt][q] = 0.0f;

    GEMM_MAINLOOP(A, Bm, C_)

    const int section = bn >> 10;   // 0=q, 1=k, 2=v (CTA-uniform)
    const float qs = 0.125f * 1.44269504088896340736f;  // 1/sqrt(64) * log2(e)

#pragma unroll
    for (int mt = 0; mt < 4; ++mt) {
#pragma unroll
        for (int rr = 0; rr < 2; ++rr) {
            const int row = bm + wm * 64 + mt * 16 + g + rr * 8;
            const int b  = row >> 11;        // row / 2048
            const int tp = row & 2047;
#pragma unroll
            for (int nt = 0; nt < 4; ++nt) {
                const int col = bn + wn * 32 + nt * 8 + 2 * t;   // even
                const int hh = (col & 1023) >> 6;
                const int d  = col & 63;
                const float v0 = acc[mt][nt][rr * 2 + 0];
                const float v1 = acc[mt][nt][rr * 2 + 1];
                const size_t dst = (((size_t)(b * 16 + hh) * 2048 + tp) << 6);
                if (section == 2) {
                    *(uint2*)(g_v + dst + d) = make_uint2(f2tf32(v0), f2tf32(v1));
                } else {
                    const int i = d >> 1;
                    const float2 cs = g_rt[tp * 32 + i];
                    const float r0 = v0 * cs.x - v1 * cs.y;
                    const float r1 = v0 * cs.y + v1 * cs.x;
                    // k-permutation p(j)=((j&3)<<1)|(j>>2) within 8-block
                    const int base = d & ~7;
                    const int j0 = d & 7;                 // even
                    const int p0 = ((j0 & 3) << 1) | (j0 >> 2);
                    const int j1 = j0 + 1;
                    const int p1 = ((j1 & 3) << 1) | (j1 >> 2);
                    if (section == 0) {
                        g_q[dst + base + p0] = f2tf32(r0 * qs);
                        g_q[dst + base + p1] = f2tf32(r1 * qs);
                    } else {
                        g_k[dst + base + p0] = f2tf32(r0);
                        g_k[dst + base + p1] = f2tf32(r1);
                    }
                }
            }
        }
    }
}

// ============================================================================
// Tensor-core flash attention v7: Bq=128, Bk=64, hd=64. 256 threads (8 warps),
// warp = 16 q-rows. Q frags in registers (LDG.64 pairs via k-permuted g_q).
// K frags = LDS.64 pairs (k-permuted g_k). K/V via 2-stage cp.async ring,
// single sync per tile, prefetch after sync. P transpose via shfl. exp2
// softmax, deferred l-sum. smem 70KB -> 2 CTAs/SM.
// ============================================================================
#define FA_KSTR 68
#define FA_VSTR 72
#define FA_KSZ  (64 * FA_KSTR)                    // 4352 words
#define FA_VSZ  (64 * FA_VSTR)                    // 4608 words
#define FA_STG  (FA_KSZ + FA_VSZ)                 // 8960 words per stage
#define FLASH_SMEM (2 * FA_STG * 4)               // 71680 bytes

__global__ void __launch_bounds__(256, 2) flash_tc()
{
    extern __shared__ uint32_t fsm[];
    const uint32_t sbase = smem_u32(fsm);

    const int bh = blockIdx.y;                // 0..63
    const int b  = bh >> 4;
    const int h  = bh & 15;
    const int q0 = blockIdx.x * 128;

    const uint32_t* Qb = g_q + (size_t)bh * T_ * HD_;
    const uint32_t* Kb = g_k + (size_t)bh * T_ * HD_;
    const uint32_t* Vb = g_v + (size_t)bh * T_ * HD_;

    const int tid  = threadIdx.x;
    const int lane = tid & 31;
    const int wid  = tid >> 5;
    const int g = lane >> 2;       // quad row
    const int t = lane & 3;        // quad col
    const int qr = wid * 16;       // warp's q-row base within tile

    // shuffle-transpose source lanes (constant per thread)
    const int src0 = (lane & ~3) | (t >> 1);
    const int src1 = src0 + 2;
    const bool todd = (t & 1);

    // ---- Q fragments in registers: permuted layout -> LDG.64 pairs ----
    uint32_t qf[8][4];
    {
        const uint32_t* qrow0 = Qb + (size_t)(q0 + qr + g) * HD_;
        const uint32_t* qrow1 = qrow0 + 8 * HD_;
#pragma unroll
        for (int c8 = 0; c8 < 8; ++c8) {
            uint2 a02 = *(const uint2*)(qrow0 + c8 * 8 + 2 * t);
            uint2 a13 = *(const uint2*)(qrow1 + c8 * 8 + 2 * t);
            qf[c8][0] = a02.x;   // k = c8*8+t
            qf[c8][2] = a02.y;   // k = c8*8+t+4
            qf[c8][1] = a13.x;
            qf[c8][3] = a13.y;
        }
    }

    // cp.async tile loader: K tile (stride 68, permuted cols verbatim) + V (72)
    auto cp_kv = [&](int k0, int s) {
        const uint32_t koff = (uint32_t)s * FA_STG;
        const uint32_t voff = koff + FA_KSZ;
#pragma unroll
        for (int p = 0; p < 4; ++p) {
            int idx = tid * 4 + p;
            int row = idx >> 4;          // 0..63
            int c4  = (idx & 15) * 4;    // word offset 0..60
            cp16(sbase + (koff + (uint32_t)row * FA_KSTR + c4) * 4,
                 Kb + (size_t)(k0 + row) * HD_ + c4);
            cp16(sbase + (voff + (uint32_t)row * FA_VSTR + c4) * 4,
                 Vb + (size_t)(k0 + row) * HD_ + c4);
        }
    };

    // online softmax state (rows qr+g, qr+g+8) in log2 domain; per-lane l.
    float m0 = -3.0e38f, m1 = -3.0e38f, l0 = 0.0f, l1 = 0.0f;
    float oacc[8][4];
#pragma unroll
    for (int nt = 0; nt < 8; ++nt)
#pragma unroll
        for (int q = 0; q < 4; ++q) oacc[nt][q] = 0.0f;

    const int NT = T_ / 64;
    cp_kv(0, 0); CP_COMMIT();

    for (int kt = 0; kt < NT; ++kt) {
        CP_WAIT0();
        __syncthreads();
        if (kt + 1 < NT) {
            cp_kv((kt + 1) * 64, (kt + 1) & 1);
            CP_COMMIT();
        }

        const int cs = kt & 1;
        const uint32_t* Ks = fsm + cs * FA_STG;
        const uint32_t* Vs = fsm + cs * FA_STG + FA_KSZ;

        // ---- S = Q K^T (log2 domain): K frag pairs via LDS.64 ----
        float sacc[8][4];
#pragma unroll
        for (int nt = 0; nt < 8; ++nt)
#pragma unroll
            for (int q = 0; q < 4; ++q) sacc[nt][q] = 0.0f;

#pragma unroll
        for (int c8 = 0; c8 < 8; ++c8) {
#pragma unroll
            for (int nt = 0; nt < 8; ++nt) {
                uint2 kk2 = *(const uint2*)(Ks + (nt * 8 + g) * FA_KSTR + c8 * 8 + 2 * t);
                uint32_t bb[2] = {kk2.x, kk2.y};
                mma16n8k8(sacc[nt], qf[c8], bb);
            }
        }

        // ---- online softmax (exp2 domain; only MAX needs quad reduce) ----
        float tm0 = -3.0e38f, tm1 = -3.0e38f;
#pragma unroll
        for (int nt = 0; nt < 8; ++nt) {
            tm0 = fmaxf(tm0, fmaxf(sacc[nt][0], sacc[nt][1]));
            tm1 = fmaxf(tm1, fmaxf(sacc[nt][2], sacc[nt][3]));
        }
#pragma unroll
        for (int off = 1; off < 4; off <<= 1) {
            tm0 = fmaxf(tm0, __shfl_xor_sync(0xffffffffu, tm0, off));
            tm1 = fmaxf(tm1, __shfl_xor_sync(0xffffffffu, tm1, off));
        }
        const float mn0 = fmaxf(m0, tm0);
        const float mn1 = fmaxf(m1, tm1);
        const float corr0 = ex2f(m0 - mn0);
        const float corr1 = ex2f(m1 - mn1);
        m0 = mn0; m1 = mn1;

        float rs0 = 0.0f, rs1 = 0.0f;
#pragma unroll
        for (int nt = 0; nt < 8; ++nt) {
            float p0 = ex2f(sacc[nt][0] - mn0);
            float p1 = ex2f(sacc[nt][1] - mn0);
            float p2 = ex2f(sacc[nt][2] - mn1);
            float p3 = ex2f(sacc[nt][3] - mn1);
            sacc[nt][0] = p0; sacc[nt][1] = p1; sacc[nt][2] = p2; sacc[nt][3] = p3;
            rs0 += p0 + p1;
            rs1 += p2 + p3;
#pragma unroll
            for (int q = 0; q < 2; ++q) { oacc[nt][q] *= corr0; oacc[nt][q + 2] *= corr1; }
        }
        l0 = l0 * corr0 + rs0;
        l1 = l1 * corr1 + rs1;

        // ---- O += P V : P A-frags built by shfl transpose of C-frags ----
#pragma unroll
        for (int kk = 0; kk < 8; ++kk) {
            float x0 = __shfl_sync(0xffffffffu, sacc[kk][0], src0);
            float x1 = __shfl_sync(0xffffffffu, sacc[kk][1], src0);
            float x2 = __shfl_sync(0xffffffffu, sacc[kk][2], src0);
            float x3 = __shfl_sync(0xffffffffu, sacc[kk][3], src0);
            float y0 = __shfl_sync(0xffffffffu, sacc[kk][0], src1);
            float y1 = __shfl_sync(0xffffffffu, sacc[kk][1], src1);
            float y2 = __shfl_sync(0xffffffffu, sacc[kk][2], src1);
            float y3 = __shfl_sync(0xffffffffu, sacc[kk][3], src1);
            uint32_t a[4];
            a[0] = f2tf32(todd ? x1 : x0);
            a[1] = f2tf32(todd ? x3 : x2);
            a[2] = f2tf32(todd ? y1 : y0);
            a[3] = f2tf32(todd ? y3 : y2);
#pragma unroll
            for (int nt = 0; nt < 8; ++nt) {
                uint32_t bb[2];
                bb[0] = Vs[(kk * 8 + t) * FA_VSTR + nt * 8 + g];
                bb[1] = Vs[(kk * 8 + t + 4) * FA_VSTR + nt * 8 + g];
                mma16n8k8(oacc[nt], a, bb);
            }
        }
    }

    // ---- epilogue: reduce l across quad, normalize, write tf32 bits ----
#pragma unroll
    for (int off = 1; off < 4; off <<= 1) {
        l0 += __shfl_xor_sync(0xffffffffu, l0, off);
        l1 += __shfl_xor_sync(0xffffffffu, l1, off);
    }
    const float rl0 = 1.0f / l0;
    const float rl1 = 1.0f / l1;
    const size_t row0 = (size_t)(b * T_ + q0 + qr + g);
    const size_t row1 = row0 + 8;
#pragma unroll
    for (int nt = 0; nt < 8; ++nt) {
        const int col = h * HD_ + nt * 8 + 2 * t;
        *(uint2*)(g_y + row0 * C_ + col) =
            make_uint2(f2tf32(oacc[nt][0] * rl0), f2tf32(oacc[nt][1] * rl0));
        *(uint2*)(g_y + row1 * C_ + col) =
            make_uint2(f2tf32(oacc[nt][2] * rl1), f2tf32(oacc[nt][3] * rl1));
    }
}

// ============================================================================
// launch
// ============================================================================
extern "C" void kernel_launch(void* const* d_in, const int* in_sizes, int n_in,
                              void* d_out, int out_size)
{
    const float* x      = (const float*)d_in[0];
    const float* w_attn = (const float*)d_in[1];
    const float* w_proj = (const float*)d_in[2];
    float* out = (float*)d_out;

    uint32_t* y_ptr; cudaGetSymbolAddress((void**)&y_ptr, g_y);
    uint32_t* xt;    cudaGetSymbolAddress((void**)&xt,  g_xt);
    uint32_t* wat;   cudaGetSymbolAddress((void**)&wat, g_wat);
    uint32_t* wpt;   cudaGetSymbolAddress((void**)&wpt, g_wpt);

    cudaFuncSetAttribute(flash_tc, cudaFuncAttributeMaxDynamicSharedMemorySize, FLASH_SMEM);
    cudaFuncSetAttribute(gemm_tc,  cudaFuncAttributeMaxDynamicSharedMemorySize, GEMM_SMEM);
    cudaFuncSetAttribute(gemm_qkv, cudaFuncAttributeMaxDynamicSharedMemorySize, GEMM_SMEM);

    // 0) convert inputs to tf32 bits; build rope table
    {
        int nx = M_ROWS * C_;
        to_tf32<<<(nx / 4 + 255) / 256, 256>>>(x, xt, nx);
        int na = QKV_N * C_;
        to_tf32<<<(na / 4 + 255) / 256, 256>>>(w_attn, wat, na);
        int np = C_ * C_;
        to_tf32<<<(np / 4 + 255) / 256, 256>>>(w_proj, wpt, np);
        rope_tab<<<(T_ * 32 + 255) / 256, 256>>>();
    }

    // 1) QKV GEMM with fused RoPE -> g_q/g_k/g_v directly
    gemm_qkv<<<dim3(QKV_N / 128, M_ROWS / 128), 256, GEMM_SMEM>>>(xt, wat);

    // 2) flash attention -> g_y (tf32 bits)
    flash_tc<<<dim3(T_ / 128, B_ * H_), 256, FLASH_SMEM>>>();

    // 3) out = y @ w_proj^T : (8192, 1024)
    gemm_tc<<<dim3(C_ / 128, M_ROWS / 128), 256, GEMM_SMEM>>>(
        y_ptr, wpt, out, M_ROWS, C_, C_);
}